// round 11
// baseline (speedup 1.0000x reference)
#include <cuda_runtime.h>
#include <cuda_bf16.h>
#include <cstdint>

// ---------------- problem constants ----------------
#define C 128
#define H 8
#define DD 16
#define OUTC 64
#define NLAYER 2

static const int NNh[3]  = {30000, 60000, 6000};
static const int XOFF[3] = {0, 30000, 90000};
#define NTOT 96000
static const int NEh[4]  = {200000, 300000, 200000, 100000};
#define ETOT 800000
static const int ESRC[4] = {0, 1, 1, 2};
// dst types per et: 1,1,2,0
#define DOFF0 0
#define DOFF1 60000
#define DOFF2 120000
#define DOFF3 126000
#define DROWS 156000
#define KOFF0 0
#define KOFF1 30000
#define KOFF2 90000
#define KOFF3 150000
#define KETROWS 156000
#define NMAT 31

// ---------------- scratch (device globals; no allocation allowed) ----------------
__device__ float    g_xs   [NTOT * C];
__device__ float    g_q    [NTOT * C];
__device__ float    g_agg  [NTOT * C];
__device__ float    g_ket  [KETROWS * C];
__device__ float    g_vet  [KETROWS * C];
__device__ int      g_cnt  [DROWS];
__device__ int      g_off  [DROWS + 1];
__device__ int      g_woff [DROWS];
__device__ int      g_part [256];
__device__ int      g_ssrc [ETOT];
__device__ float    g_kwc  [NLAYER * 4 * C * C];
__device__ float    g_vwc  [NLAYER * 4 * C * C];
__device__ float    g_kbc  [NLAYER * 4 * C];
__device__ float    g_vbc  [NLAYER * 4 * C];
__device__ uint32_t g_whi  [NMAT * 64 * C];
__device__ uint32_t g_wlo  [NMAT * 64 * C];

// ---------------- helpers ----------------
__device__ __forceinline__ float gelu_tanh(float x) {
    float x3 = x * x * x;
    return 0.5f * x * (1.0f + tanhf(0.7978845608028654f * (x + 0.044715f * x3)));
}
__device__ __forceinline__ void bf16x3_pack(float x, float y, uint32_t& hi, uint32_t& lo) {
    __nv_bfloat16 hx = __float2bfloat16_rn(x);
    __nv_bfloat16 hy = __float2bfloat16_rn(y);
    __nv_bfloat16 lx = __float2bfloat16_rn(x - __bfloat162float(hx));
    __nv_bfloat16 ly = __float2bfloat16_rn(y - __bfloat162float(hy));
    __nv_bfloat162 hp; hp.x = hx; hp.y = hy;
    __nv_bfloat162 lp; lp.x = lx; lp.y = ly;
    hi = *(uint32_t*)&hp;
    lo = *(uint32_t*)&lp;
}
__device__ __forceinline__ void mma_bf16(float* c, const uint32_t a[4], uint32_t b0, uint32_t b1) {
    asm volatile("mma.sync.aligned.m16n8k16.row.col.f32.bf16.bf16.f32 "
                 "{%0,%1,%2,%3}, {%4,%5,%6,%7}, {%8,%9}, {%0,%1,%2,%3};"
                 : "+f"(c[0]), "+f"(c[1]), "+f"(c[2]), "+f"(c[3])
                 : "r"(a[0]), "r"(a[1]), "r"(a[2]), "r"(a[3]), "r"(b0), "r"(b1));
}

// ---------------- combined K/V weights (fold a_rel / m_rel into kw / vw) ----------------
__global__ void wcomb_kernel(const float* __restrict__ kw, const float* __restrict__ kb,
                             const float* __restrict__ vw, const float* __restrict__ vb,
                             const float* __restrict__ a_rel, const float* __restrict__ m_rel)
{
    int b  = blockIdx.x;          // 0..7 == l*4+et
    int l  = b >> 2, et = b & 3;
    int si = (et == 0) ? 0 : ((et == 3) ? 2 : 1);
    const float* KW = kw + (size_t)(l * 3 + si) * C * C;
    const float* VW = vw + (size_t)(l * 3 + si) * C * C;
    const float* KB = kb + (size_t)(l * 3 + si) * C;
    const float* VB = vb + (size_t)(l * 3 + si) * C;
    const float* AR = a_rel + (size_t)b * H * DD * DD;
    const float* MR = m_rel + (size_t)b * H * DD * DD;
    float* KWC = g_kwc + (size_t)b * C * C;
    float* VWC = g_vwc + (size_t)b * C * C;

    for (int idx = threadIdx.x; idx < C * C; idx += blockDim.x) {
        int c = idx >> 7, hf = idx & 127, h = hf >> 4, f = hf & 15;
        float sk = 0.f, sv = 0.f;
        #pragma unroll
        for (int d = 0; d < DD; d++) {
            sk += KW[c * C + h * DD + d] * AR[(h * DD + d) * DD + f];
            sv += VW[c * C + h * DD + d] * MR[(h * DD + d) * DD + f];
        }
        KWC[idx] = sk; VWC[idx] = sv;
    }
    if (threadIdx.x < C) {
        int hf = threadIdx.x, h = hf >> 4, f = hf & 15;
        float sk = 0.f, sv = 0.f;
        #pragma unroll
        for (int d = 0; d < DD; d++) {
            sk += KB[h * DD + d] * AR[(h * DD + d) * DD + f];
            sv += VB[h * DD + d] * MR[(h * DD + d) * DD + f];
        }
        g_kbc[b * C + hf] = sk; g_vbc[b * C + hf] = sv;
    }
}

// ---------------- weight pre-split: fp32 [128][128] -> bf16 hi/lo [64 kpairs][128] ----------------
struct WSrc { const float* w[NMAT]; };

__global__ void wsplit_kernel(WSrc srcs)
{
    int mat = blockIdx.x;
    const float* __restrict__ W = srcs.w[mat];
    uint32_t* __restrict__ whi = g_whi + (size_t)mat * 64 * C;
    uint32_t* __restrict__ wlo = g_wlo + (size_t)mat * 64 * C;
    for (int idx = threadIdx.x; idx < 64 * C; idx += blockDim.x) {
        int kp = idx >> 7, col = idx & 127;
        float e = W[(2 * kp) * C + col];
        float o = W[(2 * kp + 1) * C + col];
        uint32_t hi, lo;
        bf16x3_pack(e, o, hi, lo);
        whi[idx] = hi; wlo[idx] = lo;
    }
}

// ---------------- CSR build: histogram -> scan -> scatter ----------------
__global__ void hist4_kernel(const int* __restrict__ d0, const int* __restrict__ d1,
                             const int* __restrict__ d2, const int* __restrict__ d3,
                             int* __restrict__ cnt)
{
    int i = blockIdx.x * 256 + threadIdx.x;
    if (i < 200000)      atomicAdd(&cnt[DOFF0 + d0[i]], 1);
    else if (i < 500000) atomicAdd(&cnt[DOFF1 + d1[i - 200000]], 1);
    else if (i < 700000) atomicAdd(&cnt[DOFF2 + d2[i - 500000]], 1);
    else if (i < ETOT)   atomicAdd(&cnt[DOFF3 + d3[i - 700000]], 1);
}

__global__ void scan_block(const int* __restrict__ cnt, int* __restrict__ off, int* __restrict__ part)
{
    __shared__ int sm[1024];
    int tid = threadIdx.x;
    int i = blockIdx.x * 1024 + tid;
    int v = (i < DROWS) ? cnt[i] : 0;
    sm[tid] = v;
    __syncthreads();
    #pragma unroll
    for (int ofs = 1; ofs < 1024; ofs <<= 1) {
        int t = (tid >= ofs) ? sm[tid - ofs] : 0;
        __syncthreads();
        sm[tid] += t;
        __syncthreads();
    }
    if (i < DROWS) off[i] = sm[tid] - v;
    if (tid == 1023) part[blockIdx.x] = sm[1023];
}

__global__ void scan_part(int* part, int nb)
{
    if (threadIdx.x == 0 && blockIdx.x == 0) {
        int s = 0;
        for (int i = 0; i < nb; i++) { int t = part[i]; part[i] = s; s += t; }
    }
}

__global__ void scan_add(int* __restrict__ off, const int* __restrict__ part,
                         int* __restrict__ woff)
{
    int i = blockIdx.x * 256 + threadIdx.x;
    if (i < DROWS) {
        int o = off[i] + part[i >> 10];
        off[i] = o;
        woff[i] = o;
    }
    if (i == DROWS) off[DROWS] = ETOT;
}

__global__ void scatter4_kernel(const int* __restrict__ s0, const int* __restrict__ d0,
                                const int* __restrict__ s1, const int* __restrict__ d1,
                                const int* __restrict__ s2, const int* __restrict__ d2,
                                const int* __restrict__ s3, const int* __restrict__ d3,
                                int* __restrict__ woffb, int* __restrict__ ssrc)
{
    int i = blockIdx.x * 256 + threadIdx.x;
    int sv, dv;
    if (i < 200000)      { sv = s0[i];          dv = DOFF0 + d0[i]; }
    else if (i < 500000) { sv = s1[i - 200000]; dv = DOFF1 + d1[i - 200000]; }
    else if (i < 700000) { sv = s2[i - 500000]; dv = DOFF2 + d2[i - 500000]; }
    else if (i < ETOT)   { sv = s3[i - 700000]; dv = DOFF3 + d3[i - 700000]; }
    else return;
    int p = atomicAdd(&woffb[dv], 1);
    ssrc[p] = sv;
}

// ---------------- fused attention: one warp per dst node, online softmax, no atomics ----------------
__device__ __forceinline__ void attn_sweep(
    const float4 q4, int lane,
    int beg, int end, int koff,
    const float* __restrict__ ket, const float* __restrict__ vet,
    float ps, float4& accOut)
{
    float m = -1e30f, den = 0.f;
    float4 a = make_float4(0.f, 0.f, 0.f, 0.f);
    int s = (beg < end) ? __ldg(&g_ssrc[beg]) : 0;
    for (int p = beg; p < end; p++) {
        int sn = (p + 1 < end) ? __ldg(&g_ssrc[p + 1]) : 0;
        float4 k4 = ((const float4*)(ket + (size_t)(koff + s) * 128))[lane];
        float4 v4 = ((const float4*)(vet + (size_t)(koff + s) * 128))[lane];
        float dt = q4.x * k4.x + q4.y * k4.y + q4.z * k4.z + q4.w * k4.w;
        dt += __shfl_xor_sync(0xffffffffu, dt, 1);
        dt += __shfl_xor_sync(0xffffffffu, dt, 2);
        float al = dt * ps;
        float mn = fmaxf(m, al);
        float sc = __expf(m - mn);
        float ex = __expf(al - mn);
        den = den * sc + ex;
        a.x = a.x * sc + ex * v4.x;
        a.y = a.y * sc + ex * v4.y;
        a.z = a.z * sc + ex * v4.z;
        a.w = a.w * sc + ex * v4.w;
        m = mn;
        s = sn;
    }
    float w = 1.f / (den + 1e-16f);
    accOut.x += a.x * w; accOut.y += a.y * w;
    accOut.z += a.z * w; accOut.w += a.w * w;
}

// Launch A: et0 (road, init-write), et2 (region), et3 (poi).
// Combined ket/vet working set ~96 MB < L2 -> L2-resident random reads.
__global__ void __launch_bounds__(256)
attn_init(const float* __restrict__ q, const float* __restrict__ ket,
          const float* __restrict__ vet, const int* __restrict__ off,
          float* __restrict__ agg, const float* __restrict__ p_rel, int layer)
{
    int w = (blockIdx.x * 256 + threadIdx.x) >> 5;
    if (w >= NTOT) return;
    int lane = threadIdx.x & 31;
    int h = lane >> 2;

    float4 acc = make_float4(0.f, 0.f, 0.f, 0.f);
    int node;

    if (w < 60000) {
        int d = w;
        node = 30000 + d;
        float4 q4 = ((const float4*)(q + (size_t)node * 128))[lane];
        attn_sweep(q4, lane, off[DOFF0 + d], off[DOFF0 + d + 1], KOFF0, ket, vet,
                   p_rel[(layer * 4 + 0) * H + h] * 0.25f, acc);
    } else if (w < 90000) {
        int d = w - 60000;
        node = d;
        float4 q4 = ((const float4*)(q + (size_t)node * 128))[lane];
        attn_sweep(q4, lane, off[DOFF3 + d], off[DOFF3 + d + 1], KOFF3, ket, vet,
                   p_rel[(layer * 4 + 3) * H + h] * 0.25f, acc);
    } else {
        int d = w - 90000;
        node = 90000 + d;
        float4 q4 = ((const float4*)(q + (size_t)node * 128))[lane];
        attn_sweep(q4, lane, off[DOFF2 + d], off[DOFF2 + d + 1], KOFF2, ket, vet,
                   p_rel[(layer * 4 + 2) * H + h] * 0.25f, acc);
    }
    ((float4*)(agg + (size_t)node * 128))[lane] = acc;
}

// Launch B: et1 only (road, accumulate into agg). Working set ~60 MB < L2.
__global__ void __launch_bounds__(256)
attn_et1(const float* __restrict__ q, const float* __restrict__ ket,
         const float* __restrict__ vet, const int* __restrict__ off,
         float* __restrict__ agg, const float* __restrict__ p_rel, int layer)
{
    int d = (blockIdx.x * 256 + threadIdx.x) >> 5;
    if (d >= 60000) return;
    int lane = threadIdx.x & 31;
    int h = lane >> 2;
    int node = 30000 + d;

    float4 acc = make_float4(0.f, 0.f, 0.f, 0.f);
    float4 q4 = ((const float4*)(q + (size_t)node * 128))[lane];
    attn_sweep(q4, lane, off[DOFF1 + d], off[DOFF1 + d + 1], KOFF1, ket, vet,
               p_rel[(layer * 4 + 1) * H + h] * 0.25f, acc);

    float4* dst = (float4*)(agg + (size_t)node * 128) + lane;
    float4 old = *dst;
    old.x += acc.x; old.y += acc.y; old.z += acc.z; old.w += acc.w;
    *dst = old;
}

// ---------------- multi-job bf16x3 tensor-core GEMM, pre-split weights ----------------
// (byte-identical to the R9 kernel that passed on HW)
// epi bits: 0x1 relu, 0x2 skip-gate, 0x4 gelu on A load
struct GemmJob {
    const float *A, *bias;
    float *Out;
    const float *skipx, *skipv;
    int mat, M, blk0, epi;
};
struct Jobs11 { GemmJob j[11]; };

#define APK 36     // uint32 stride: 32 k-pairs + pad
#define BPK 136    // uint32 stride: 128 cols + pad
#define A_HI 0
#define A_LO (128 * APK)
#define B_HI (2 * 128 * APK)
#define B_LO (2 * 128 * APK + 32 * BPK)
#define GEMM_SMEM ((2 * 128 * APK + 2 * 32 * BPK) * 4)

__global__ void __launch_bounds__(256)
gemm_bf16x3_jobs(Jobs11 jobs, int njobs,
                 const uint32_t* __restrict__ whi, const uint32_t* __restrict__ wlo)
{
    extern __shared__ uint32_t sm[];

    int bid = blockIdx.x;
    int j = 0;
    while (j + 1 < njobs && bid >= jobs.j[j + 1].blk0) j++;
    const GemmJob& J = jobs.j[j];

    int tid  = threadIdx.x;
    int lane = tid & 31, warp = tid >> 5;
    int wm = warp & 1, wn = warp >> 1;     // 2 x 4 warp grid, warp tile 64x32
    int g = lane >> 2, t = lane & 3;
    int row0 = (bid - J.blk0) * 128;
    bool doGelu = (J.epi & 4) != 0;
    const uint32_t* WH = whi + (size_t)J.mat * 64 * 128;
    const uint32_t* WL = wlo + (size_t)J.mat * 64 * 128;

    float acc[4][4][4];
    #pragma unroll
    for (int a = 0; a < 4; a++)
        #pragma unroll
        for (int b = 0; b < 4; b++)
            #pragma unroll
            for (int c = 0; c < 4; c++) acc[a][b][c] = 0.f;

    #pragma unroll
    for (int ch = 0; ch < 2; ch++) {
        int k0 = ch * 64;
        // ---- A tile: 128 rows x 64 k, split+pack to bf16 hi/lo pairs ----
        {
            int r  = tid >> 4;            // 0..15
            int c4 = (tid & 15) * 4;      // 0..60 (k offset)
            #pragma unroll
            for (int p = 0; p < 8; p++) {
                int rr = r + p * 16;
                int gr = row0 + rr;
                float4 v = make_float4(0.f, 0.f, 0.f, 0.f);
                if (gr < J.M) v = *(const float4*)(J.A + (size_t)gr * 128 + k0 + c4);
                if (doGelu) {
                    v.x = gelu_tanh(v.x); v.y = gelu_tanh(v.y);
                    v.z = gelu_tanh(v.z); v.w = gelu_tanh(v.w);
                }
                uint32_t h0, l0, h1, l1;
                bf16x3_pack(v.x, v.y, h0, l0);
                bf16x3_pack(v.z, v.w, h1, l1);
                int base = rr * APK + (c4 >> 1);
                *(uint2*)&sm[A_HI + base] = make_uint2(h0, h1);
                *(uint2*)&sm[A_LO + base] = make_uint2(l0, l1);
            }
        }
        // ---- B tile: copy pre-split weights [32 kpairs][128 cols] ----
        {
            int kp0 = tid >> 5;           // 0..7
            int c4  = (tid & 31) * 4;     // 0..124
            const uint32_t* WHc = WH + ch * 32 * 128;
            const uint32_t* WLc = WL + ch * 32 * 128;
            #pragma unroll
            for (int p = 0; p < 4; p++) {
                int kp = kp0 + p * 8;
                uint4 hv = *(const uint4*)&WHc[kp * 128 + c4];
                uint4 lv = *(const uint4*)&WLc[kp * 128 + c4];
                *(uint4*)&sm[B_HI + kp * BPK + c4] = hv;
                *(uint4*)&sm[B_LO + kp * BPK + c4] = lv;
            }
        }
        __syncthreads();

        #pragma unroll
        for (int ks = 0; ks < 4; ks++) {      // 4 x k16 steps per 64-k chunk
            int kp = ks * 8;
            uint32_t ahi[4][4], alo[4][4];
            #pragma unroll
            for (int mf = 0; mf < 4; mf++) {
                int rm = wm * 64 + mf * 16;
                int i0 = (rm + g)     * APK + kp + t;
                int i1 = (rm + g + 8) * APK + kp + t;
                ahi[mf][0] = sm[A_HI + i0];
                ahi[mf][1] = sm[A_HI + i1];
                ahi[mf][2] = sm[A_HI + i0 + 4];
                ahi[mf][3] = sm[A_HI + i1 + 4];
                alo[mf][0] = sm[A_LO + i0];
                alo[mf][1] = sm[A_LO + i1];
                alo[mf][2] = sm[A_LO + i0 + 4];
                alo[mf][3] = sm[A_LO + i1 + 4];
            }
            #pragma unroll
            for (int nf = 0; nf < 4; nf++) {
                int cn = wn * 32 + nf * 8 + g;
                uint32_t bh0 = sm[B_HI + (kp + t)     * BPK + cn];
                uint32_t bh1 = sm[B_HI + (kp + t + 4) * BPK + cn];
                uint32_t bl0 = sm[B_LO + (kp + t)     * BPK + cn];
                uint32_t bl1 = sm[B_LO + (kp + t + 4) * BPK + cn];
                #pragma unroll
                for (int mf = 0; mf < 4; mf++) {
                    mma_bf16(acc[mf][nf], ahi[mf], bh0, bh1);
                    mma_bf16(acc[mf][nf], ahi[mf], bl0, bl1);
                    mma_bf16(acc[mf][nf], alo[mf], bh0, bh1);
                }
            }
        }
        __syncthreads();
    }

    // epilogue
    float beta = 1.f, omb = 0.f;
    if (J.epi & 2) {
        float sv = *J.skipv;
        beta = 1.f / (1.f + __expf(-sv));
        omb  = 1.f - beta;
    }
    bool relu = (J.epi & 1) || (J.epi & 2);

    #pragma unroll
    for (int nf = 0; nf < 4; nf++) {
        int col = wn * 32 + nf * 8 + t * 2;
        float bc0 = J.bias[col], bc1 = J.bias[col + 1];
        #pragma unroll
        for (int mf = 0; mf < 4; mf++) {
            int r0 = row0 + wm * 64 + mf * 16 + g;
            int r1 = r0 + 8;
            float o00 = acc[mf][nf][0] + bc0, o01 = acc[mf][nf][1] + bc1;
            float o10 = acc[mf][nf][2] + bc0, o11 = acc[mf][nf][3] + bc1;
            if (J.epi & 2) {
                if (r0 < J.M) {
                    float2 s = *(const float2*)(J.skipx + (size_t)r0 * 128 + col);
                    o00 = beta * o00 + omb * s.x;
                    o01 = beta * o01 + omb * s.y;
                }
                if (r1 < J.M) {
                    float2 s = *(const float2*)(J.skipx + (size_t)r1 * 128 + col);
                    o10 = beta * o10 + omb * s.x;
                    o11 = beta * o11 + omb * s.y;
                }
            }
            if (relu) {
                o00 = fmaxf(o00, 0.f); o01 = fmaxf(o01, 0.f);
                o10 = fmaxf(o10, 0.f); o11 = fmaxf(o11, 0.f);
            }
            if (r0 < J.M) *(float2*)(J.Out + (size_t)r0 * 128 + col) = make_float2(o00, o01);
            if (r1 < J.M) *(float2*)(J.Out + (size_t)r1 * 128 + col) = make_float2(o10, o11);
        }
    }
}

// ---------------- scalar GEMM for the final [128 x 64] projection ----------------
__global__ void __launch_bounds__(256)
gemm_out64(const float* __restrict__ A, const float* __restrict__ W,
           const float* __restrict__ bias, float* __restrict__ Out, int M)
{
    constexpr int BN = 64, CT = BN / 4, BM = (256 / CT) * 8, BK = 32, AP = BM + 4;
    __shared__ float As[BK][AP];
    __shared__ float Bs[BK][BN];

    int tid = threadIdx.x;
    int row0 = blockIdx.x * BM;
    int trow = (tid / CT) * 8;
    int tcol = (tid % CT) * 4;

    float acc[8][4];
    #pragma unroll
    for (int r = 0; r < 8; r++)
        #pragma unroll
        for (int c = 0; c < 4; c++) acc[r][c] = 0.f;

    for (int k0 = 0; k0 < 128; k0 += BK) {
        #pragma unroll
        for (int i = 0; i < (BM * 8) / 256; ++i) {
            int id = tid + i * 256;
            int r = id >> 3, kq = id & 7;
            float4 v = make_float4(0.f, 0.f, 0.f, 0.f);
            int gr = row0 + r;
            if (gr < M) v = *(const float4*)(A + (size_t)gr * 128 + k0 + kq * 4);
            As[kq * 4 + 0][r] = v.x; As[kq * 4 + 1][r] = v.y;
            As[kq * 4 + 2][r] = v.z; As[kq * 4 + 3][r] = v.w;
        }
        #pragma unroll
        for (int i = 0; i < (8 * BN) / 256; ++i) {
            int id = tid + i * 256;
            int kr = id / CT, c4 = (id % CT) * 4;
            *(float4*)&Bs[kr][c4] = *(const float4*)(W + (size_t)(k0 + kr) * BN + c4);
        }
        __syncthreads();
        #pragma unroll
        for (int k = 0; k < BK; ++k) {
            float4 b = *(float4*)&Bs[k][tcol];
            #pragma unroll
            for (int r = 0; r < 8; r++) {
                float a = As[k][trow + r];
                acc[r][0] += a * b.x; acc[r][1] += a * b.y;
                acc[r][2] += a * b.z; acc[r][3] += a * b.w;
            }
        }
        __syncthreads();
    }
    float b0 = bias[tcol], b1 = bias[tcol + 1], b2 = bias[tcol + 2], b3 = bias[tcol + 3];
    #pragma unroll
    for (int r = 0; r < 8; r++) {
        int gr = row0 + trow + r;
        if (gr >= M) break;
        float4 o = make_float4(acc[r][0] + b0, acc[r][1] + b1, acc[r][2] + b2, acc[r][3] + b3);
        *(float4*)(Out + (size_t)gr * BN + tcol) = o;
    }
}

// ---------------- host orchestration ----------------
static inline int nb128(int m) { return (m + 127) / 128; }

extern "C" void kernel_launch(void* const* d_in, const int* in_sizes, int n_in,
                              void* d_out, int out_size)
{
    const float* x_in[3] = {(const float*)d_in[0], (const float*)d_in[1], (const float*)d_in[2]};
    const int* esrc[4] = {(const int*)d_in[3], (const int*)d_in[5], (const int*)d_in[7], (const int*)d_in[9]};
    const int* edst[4] = {(const int*)d_in[4], (const int*)d_in[6], (const int*)d_in[8], (const int*)d_in[10]};
    const float* lin_w = (const float*)d_in[11];
    const float* lin_b = (const float*)d_in[12];
    const float* kw    = (const float*)d_in[13];
    const float* qw    = (const float*)d_in[14];
    const float* vw    = (const float*)d_in[15];
    const float* aw    = (const float*)d_in[16];
    const float* kb    = (const float*)d_in[17];
    const float* qb    = (const float*)d_in[18];
    const float* vb    = (const float*)d_in[19];
    const float* ab    = (const float*)d_in[20];
    const float* a_rel = (const float*)d_in[21];
    const float* m_rel = (const float*)d_in[22];
    const float* p_rel = (const float*)d_in[23];
    const float* skip  = (const float*)d_in[24];
    const float* out_w = (const float*)d_in[25];
    const float* out_b = (const float*)d_in[26];
    float* out = (float*)d_out;

    float *xs, *q, *agg, *ket, *vet, *kwc, *vwc, *kbc, *vbc;
    int *cnt, *off, *woff, *part, *ssrc;
    uint32_t *whi, *wlo;
    cudaGetSymbolAddress((void**)&xs,   g_xs);
    cudaGetSymbolAddress((void**)&q,    g_q);
    cudaGetSymbolAddress((void**)&agg,  g_agg);
    cudaGetSymbolAddress((void**)&ket,  g_ket);
    cudaGetSymbolAddress((void**)&vet,  g_vet);
    cudaGetSymbolAddress((void**)&cnt,  g_cnt);
    cudaGetSymbolAddress((void**)&off,  g_off);
    cudaGetSymbolAddress((void**)&woff, g_woff);
    cudaGetSymbolAddress((void**)&part, g_part);
    cudaGetSymbolAddress((void**)&ssrc, g_ssrc);
    cudaGetSymbolAddress((void**)&kwc,  g_kwc);
    cudaGetSymbolAddress((void**)&vwc,  g_vwc);
    cudaGetSymbolAddress((void**)&kbc,  g_kbc);
    cudaGetSymbolAddress((void**)&vbc,  g_vbc);
    cudaGetSymbolAddress((void**)&whi,  g_whi);
    cudaGetSymbolAddress((void**)&wlo,  g_wlo);

    cudaFuncSetAttribute(gemm_bf16x3_jobs, cudaFuncAttributeMaxDynamicSharedMemorySize, GEMM_SMEM);

    // ---- CSR build (edges are layer-invariant: build once) ----
    cudaMemsetAsync(cnt, 0, DROWS * sizeof(int));
    hist4_kernel<<<(ETOT + 255) / 256, 256>>>(edst[0], edst[1], edst[2], edst[3], cnt);
    scan_block<<<(DROWS + 1023) / 1024, 1024>>>(cnt, off, part);
    scan_part<<<1, 32>>>(part, (DROWS + 1023) / 1024);
    scan_add<<<(DROWS + 256) / 256, 256>>>(off, part, woff);
    scatter4_kernel<<<(ETOT + 255) / 256, 256>>>(esrc[0], edst[0], esrc[1], edst[1],
                                                 esrc[2], edst[2], esrc[3], edst[3],
                                                 woff, ssrc);

    // ---- fold a_rel/m_rel into K/V weights, then pre-split all weights to bf16 hi/lo ----
    wcomb_kernel<<<8, 256>>>(kw, kb, vw, vb, a_rel, m_rel);
    {
        WSrc ws;
        for (int i = 0; i < 3; i++) ws.w[i] = lin_w + (size_t)i * C * C;                       // 0..2
        for (int li = 0; li < 6; li++) ws.w[3 + li] = qw + (size_t)li * C * C;                 // 3..8
        for (int le = 0; le < 8; le++) ws.w[9 + le] = kwc + (size_t)le * C * C;                // 9..16
        for (int le = 0; le < 8; le++) ws.w[17 + le] = vwc + (size_t)le * C * C;               // 17..24
        for (int li = 0; li < 6; li++) ws.w[25 + li] = aw + (size_t)li * C * C;                // 25..30
        wsplit_kernel<<<NMAT, 256>>>(ws);
    }

    // ---- input linear + relu (3 jobs, one launch) ----
    {
        Jobs11 js{}; int nj = 0, blk = 0;
        for (int i = 0; i < 3; i++) {
            GemmJob& J = js.j[nj++];
            J.A = x_in[i]; J.mat = i; J.bias = lin_b + i * C;
            J.Out = xs + (size_t)XOFF[i] * C; J.M = NNh[i]; J.blk0 = blk; J.epi = 1;
            J.skipx = nullptr; J.skipv = nullptr;
            blk += nb128(NNh[i]);
        }
        gemm_bf16x3_jobs<<<blk, 256, GEMM_SMEM>>>(js, nj, whi, wlo);
    }

    static const int KOFFh[4] = {KOFF0, KOFF1, KOFF2, KOFF3};
    for (int l = 0; l < NLAYER; l++) {
        // ---- Q + K_et + V_et projections (11 jobs, one launch) ----
        {
            Jobs11 js{}; int nj = 0, blk = 0;
            for (int i = 0; i < 3; i++) {
                GemmJob& J = js.j[nj++];
                J.A = xs + (size_t)XOFF[i] * C;
                J.mat = 3 + l * 3 + i;
                J.bias = qb + (l * 3 + i) * C;
                J.Out = q + (size_t)XOFF[i] * C;
                J.M = NNh[i]; J.blk0 = blk; J.epi = 0;
                blk += nb128(NNh[i]);
            }
            for (int et = 0; et < 4; et++) {
                int si = ESRC[et];
                {
                    GemmJob& J = js.j[nj++];
                    J.A = xs + (size_t)XOFF[si] * C;
                    J.mat = 9 + l * 4 + et;
                    J.bias = kbc + (l * 4 + et) * C;
                    J.Out = ket + (size_t)KOFFh[et] * C;
                    J.M = NNh[si]; J.blk0 = blk; J.epi = 0;
                    blk += nb128(NNh[si]);
                }
                {
                    GemmJob& J = js.j[nj++];
                    J.A = xs + (size_t)XOFF[si] * C;
                    J.mat = 17 + l * 4 + et;
                    J.bias = vbc + (l * 4 + et) * C;
                    J.Out = vet + (size_t)KOFFh[et] * C;
                    J.M = NNh[si]; J.blk0 = blk; J.epi = 0;
                    blk += nb128(NNh[si]);
                }
            }
            gemm_bf16x3_jobs<<<blk, 256, GEMM_SMEM>>>(js, nj, whi, wlo);
        }

        // ---- fused attention, split for L2 residency: (et0+et2+et3) then et1 ----
        attn_init<<<(NTOT * 32 + 255) / 256, 256>>>(q, ket, vet, off, agg, p_rel, l);
        attn_et1<<<(60000 * 32 + 255) / 256, 256>>>(q, ket, vet, off, agg, p_rel, l);

        // ---- attn-out projection, gelu fused on A, skip-gate + relu epilogue ----
        {
            Jobs11 js{}; int nj = 0, blk = 0;
            for (int i = 0; i < 3; i++) {
                GemmJob& J = js.j[nj++];
                J.A = agg + (size_t)XOFF[i] * C;
                J.mat = 25 + l * 3 + i;
                J.bias = ab + (l * 3 + i) * C;
                J.Out = xs + (size_t)XOFF[i] * C;
                J.skipx = xs + (size_t)XOFF[i] * C;
                J.skipv = skip + l * 3 + i;
                J.M = NNh[i]; J.blk0 = blk; J.epi = 2 | 4;
                blk += nb128(NNh[i]);
            }
            gemm_bf16x3_jobs<<<blk, 256, GEMM_SMEM>>>(js, nj, whi, wlo);
        }
    }

    // ---- final output projection [N,128] @ [128,64] ----
    for (int i = 0; i < 3; i++) {
        dim3 grid((NNh[i] + 127) / 128);
        gemm_out64<<<grid, 256>>>(xs + (size_t)XOFF[i] * C, out_w, out_b,
                                  out + (size_t)XOFF[i] * OUTC, NNh[i]);
    }
}

// round 13
// speedup vs baseline: 1.1611x; 1.1611x over previous
#include <cuda_runtime.h>
#include <cuda_bf16.h>
#include <cstdint>

// ---------------- problem constants ----------------
#define C 128
#define H 8
#define DD 16
#define OUTC 64
#define NLAYER 2

static const int NNh[3]  = {30000, 60000, 6000};
static const int XOFF[3] = {0, 30000, 90000};
#define NTOT 96000
static const int NEh[4]  = {200000, 300000, 200000, 100000};
#define ETOT 800000
static const int ESRC[4] = {0, 1, 1, 2};
// dst types per et: 1,1,2,0
#define DOFF0 0
#define DOFF1 60000
#define DOFF2 120000
#define DOFF3 126000
#define DROWS 156000
#define KOFF0 0
#define KOFF1 30000
#define KOFF2 90000
#define KOFF3 150000
#define KETROWS 156000
#define NMAT 31

// ---------------- scratch (device globals; no allocation allowed) ----------------
__device__ float    g_xs   [NTOT * C];
__device__ float    g_q    [NTOT * C];
__device__ float    g_agg  [NTOT * C];
__device__ float    g_ket  [KETROWS * C];
__device__ float    g_vet  [KETROWS * C];
__device__ int      g_cnt  [DROWS];
__device__ int      g_off  [DROWS + 1];
__device__ int      g_woff [DROWS];
__device__ int      g_part [256];
__device__ int      g_ssrc [ETOT];
__device__ float    g_kwc  [NLAYER * 4 * C * C];
__device__ float    g_vwc  [NLAYER * 4 * C * C];
__device__ float    g_kbc  [NLAYER * 4 * C];
__device__ float    g_vbc  [NLAYER * 4 * C];
__device__ uint32_t g_whi  [NMAT * 64 * C];
__device__ uint32_t g_wlo  [NMAT * 64 * C];

// ---------------- helpers ----------------
__device__ __forceinline__ float gelu_tanh(float x) {
    float x3 = x * x * x;
    return 0.5f * x * (1.0f + tanhf(0.7978845608028654f * (x + 0.044715f * x3)));
}
__device__ __forceinline__ void bf16x3_pack(float x, float y, uint32_t& hi, uint32_t& lo) {
    __nv_bfloat16 hx = __float2bfloat16_rn(x);
    __nv_bfloat16 hy = __float2bfloat16_rn(y);
    __nv_bfloat16 lx = __float2bfloat16_rn(x - __bfloat162float(hx));
    __nv_bfloat16 ly = __float2bfloat16_rn(y - __bfloat162float(hy));
    __nv_bfloat162 hp; hp.x = hx; hp.y = hy;
    __nv_bfloat162 lp; lp.x = lx; lp.y = ly;
    hi = *(uint32_t*)&hp;
    lo = *(uint32_t*)&lp;
}
__device__ __forceinline__ void mma_bf16(float* c, const uint32_t a[4], uint32_t b0, uint32_t b1) {
    asm volatile("mma.sync.aligned.m16n8k16.row.col.f32.bf16.bf16.f32 "
                 "{%0,%1,%2,%3}, {%4,%5,%6,%7}, {%8,%9}, {%0,%1,%2,%3};"
                 : "+f"(c[0]), "+f"(c[1]), "+f"(c[2]), "+f"(c[3])
                 : "r"(a[0]), "r"(a[1]), "r"(a[2]), "r"(a[3]), "r"(b0), "r"(b1));
}

// ---------------- combined K/V weights (fold a_rel / m_rel into kw / vw) ----------------
__global__ void wcomb_kernel(const float* __restrict__ kw, const float* __restrict__ kb,
                             const float* __restrict__ vw, const float* __restrict__ vb,
                             const float* __restrict__ a_rel, const float* __restrict__ m_rel)
{
    int b  = blockIdx.x;          // 0..7 == l*4+et
    int l  = b >> 2, et = b & 3;
    int si = (et == 0) ? 0 : ((et == 3) ? 2 : 1);
    const float* KW = kw + (size_t)(l * 3 + si) * C * C;
    const float* VW = vw + (size_t)(l * 3 + si) * C * C;
    const float* KB = kb + (size_t)(l * 3 + si) * C;
    const float* VB = vb + (size_t)(l * 3 + si) * C;
    const float* AR = a_rel + (size_t)b * H * DD * DD;
    const float* MR = m_rel + (size_t)b * H * DD * DD;
    float* KWC = g_kwc + (size_t)b * C * C;
    float* VWC = g_vwc + (size_t)b * C * C;

    for (int idx = threadIdx.x; idx < C * C; idx += blockDim.x) {
        int c = idx >> 7, hf = idx & 127, h = hf >> 4, f = hf & 15;
        float sk = 0.f, sv = 0.f;
        #pragma unroll
        for (int d = 0; d < DD; d++) {
            sk += KW[c * C + h * DD + d] * AR[(h * DD + d) * DD + f];
            sv += VW[c * C + h * DD + d] * MR[(h * DD + d) * DD + f];
        }
        KWC[idx] = sk; VWC[idx] = sv;
    }
    if (threadIdx.x < C) {
        int hf = threadIdx.x, h = hf >> 4, f = hf & 15;
        float sk = 0.f, sv = 0.f;
        #pragma unroll
        for (int d = 0; d < DD; d++) {
            sk += KB[h * DD + d] * AR[(h * DD + d) * DD + f];
            sv += VB[h * DD + d] * MR[(h * DD + d) * DD + f];
        }
        g_kbc[b * C + hf] = sk; g_vbc[b * C + hf] = sv;
    }
}

// ---------------- weight pre-split: fp32 [128][128] -> bf16 hi/lo [64 kpairs][128] ----------------
struct WSrc { const float* w[NMAT]; };

__global__ void wsplit_kernel(WSrc srcs)
{
    int mat = blockIdx.x;
    const float* __restrict__ W = srcs.w[mat];
    uint32_t* __restrict__ whi = g_whi + (size_t)mat * 64 * C;
    uint32_t* __restrict__ wlo = g_wlo + (size_t)mat * 64 * C;
    for (int idx = threadIdx.x; idx < 64 * C; idx += blockDim.x) {
        int kp = idx >> 7, col = idx & 127;
        float e = W[(2 * kp) * C + col];
        float o = W[(2 * kp + 1) * C + col];
        uint32_t hi, lo;
        bf16x3_pack(e, o, hi, lo);
        whi[idx] = hi; wlo[idx] = lo;
    }
}

// ---------------- CSR build: histogram -> scan -> scatter ----------------
__global__ void hist4_kernel(const int* __restrict__ d0, const int* __restrict__ d1,
                             const int* __restrict__ d2, const int* __restrict__ d3,
                             int* __restrict__ cnt)
{
    int i = blockIdx.x * 256 + threadIdx.x;
    if (i < 200000)      atomicAdd(&cnt[DOFF0 + d0[i]], 1);
    else if (i < 500000) atomicAdd(&cnt[DOFF1 + d1[i - 200000]], 1);
    else if (i < 700000) atomicAdd(&cnt[DOFF2 + d2[i - 500000]], 1);
    else if (i < ETOT)   atomicAdd(&cnt[DOFF3 + d3[i - 700000]], 1);
}

__global__ void scan_block(const int* __restrict__ cnt, int* __restrict__ off, int* __restrict__ part)
{
    __shared__ int sm[1024];
    int tid = threadIdx.x;
    int i = blockIdx.x * 1024 + tid;
    int v = (i < DROWS) ? cnt[i] : 0;
    sm[tid] = v;
    __syncthreads();
    #pragma unroll
    for (int ofs = 1; ofs < 1024; ofs <<= 1) {
        int t = (tid >= ofs) ? sm[tid - ofs] : 0;
        __syncthreads();
        sm[tid] += t;
        __syncthreads();
    }
    if (i < DROWS) off[i] = sm[tid] - v;
    if (tid == 1023) part[blockIdx.x] = sm[1023];
}

__global__ void scan_part(int* part, int nb)
{
    if (threadIdx.x == 0 && blockIdx.x == 0) {
        int s = 0;
        for (int i = 0; i < nb; i++) { int t = part[i]; part[i] = s; s += t; }
    }
}

__global__ void scan_add(int* __restrict__ off, const int* __restrict__ part,
                         int* __restrict__ woff)
{
    int i = blockIdx.x * 256 + threadIdx.x;
    if (i < DROWS) {
        int o = off[i] + part[i >> 10];
        off[i] = o;
        woff[i] = o;
    }
    if (i == DROWS) off[DROWS] = ETOT;
}

__global__ void scatter4_kernel(const int* __restrict__ s0, const int* __restrict__ d0,
                                const int* __restrict__ s1, const int* __restrict__ d1,
                                const int* __restrict__ s2, const int* __restrict__ d2,
                                const int* __restrict__ s3, const int* __restrict__ d3,
                                int* __restrict__ woffb, int* __restrict__ ssrc)
{
    int i = blockIdx.x * 256 + threadIdx.x;
    int sv, dv;
    if (i < 200000)      { sv = s0[i];          dv = DOFF0 + d0[i]; }
    else if (i < 500000) { sv = s1[i - 200000]; dv = DOFF1 + d1[i - 200000]; }
    else if (i < 700000) { sv = s2[i - 500000]; dv = DOFF2 + d2[i - 500000]; }
    else if (i < ETOT)   { sv = s3[i - 700000]; dv = DOFF3 + d3[i - 700000]; }
    else return;
    int p = atomicAdd(&woffb[dv], 1);
    ssrc[p] = sv;
}

// ---------------- fused attention: one warp per dst node, online softmax, no atomics ----------------
__device__ __forceinline__ void attn_sweep(
    const float4 q4, int lane,
    int beg, int end, int koff,
    const float* __restrict__ ket, const float* __restrict__ vet,
    float ps, float4& accOut)
{
    float m = -1e30f, den = 0.f;
    float4 a = make_float4(0.f, 0.f, 0.f, 0.f);
    int s = (beg < end) ? __ldg(&g_ssrc[beg]) : 0;
    for (int p = beg; p < end; p++) {
        int sn = (p + 1 < end) ? __ldg(&g_ssrc[p + 1]) : 0;
        float4 k4 = ((const float4*)(ket + (size_t)(koff + s) * 128))[lane];
        float4 v4 = ((const float4*)(vet + (size_t)(koff + s) * 128))[lane];
        float dt = q4.x * k4.x + q4.y * k4.y + q4.z * k4.z + q4.w * k4.w;
        dt += __shfl_xor_sync(0xffffffffu, dt, 1);
        dt += __shfl_xor_sync(0xffffffffu, dt, 2);
        float al = dt * ps;
        float mn = fmaxf(m, al);
        float sc = __expf(m - mn);
        float ex = __expf(al - mn);
        den = den * sc + ex;
        a.x = a.x * sc + ex * v4.x;
        a.y = a.y * sc + ex * v4.y;
        a.z = a.z * sc + ex * v4.z;
        a.w = a.w * sc + ex * v4.w;
        m = mn;
        s = sn;
    }
    float w = 1.f / (den + 1e-16f);
    accOut.x += a.x * w; accOut.y += a.y * w;
    accOut.z += a.z * w; accOut.w += a.w * w;
}

__global__ void __launch_bounds__(256)
attn_fused(const float* __restrict__ q, const float* __restrict__ ket,
           const float* __restrict__ vet, const int* __restrict__ off,
           float* __restrict__ agg, const float* __restrict__ p_rel, int layer)
{
    int w = (blockIdx.x * 256 + threadIdx.x) >> 5;
    if (w >= NTOT) return;
    int lane = threadIdx.x & 31;
    int h = lane >> 2;

    float4 acc = make_float4(0.f, 0.f, 0.f, 0.f);
    int node;

    if (w < 60000) {
        int d = w;
        node = 30000 + d;
        float4 q4 = ((const float4*)(q + (size_t)node * 128))[lane];
        attn_sweep(q4, lane, off[DOFF0 + d], off[DOFF0 + d + 1], KOFF0, ket, vet,
                   p_rel[(layer * 4 + 0) * H + h] * 0.25f, acc);
        attn_sweep(q4, lane, off[DOFF1 + d], off[DOFF1 + d + 1], KOFF1, ket, vet,
                   p_rel[(layer * 4 + 1) * H + h] * 0.25f, acc);
    } else if (w < 90000) {
        int d = w - 60000;
        node = d;
        float4 q4 = ((const float4*)(q + (size_t)node * 128))[lane];
        attn_sweep(q4, lane, off[DOFF3 + d], off[DOFF3 + d + 1], KOFF3, ket, vet,
                   p_rel[(layer * 4 + 3) * H + h] * 0.25f, acc);
    } else {
        int d = w - 90000;
        node = 90000 + d;
        float4 q4 = ((const float4*)(q + (size_t)node * 128))[lane];
        attn_sweep(q4, lane, off[DOFF2 + d], off[DOFF2 + d + 1], KOFF2, ket, vet,
                   p_rel[(layer * 4 + 2) * H + h] * 0.25f, acc);
    }
    ((float4*)(agg + (size_t)node * 128))[lane] = acc;
}

// ---------------- multi-job bf16x3 tensor-core GEMM, pre-split weights ----------------
// (proven on HW) epi bits: 0x1 relu, 0x2 skip-gate, 0x4 gelu on A load
struct GemmJob {
    const float *A, *bias;
    float *Out;
    const float *skipx, *skipv;
    int mat, M, blk0, epi;
};
struct Jobs11 { GemmJob j[11]; };

#define APK 36     // uint32 stride: 32 k-pairs + pad
#define BPK 136    // uint32 stride: 128 cols + pad
#define A_HI 0
#define A_LO (128 * APK)
#define B_HI (2 * 128 * APK)
#define B_LO (2 * 128 * APK + 32 * BPK)
#define GEMM_SMEM ((2 * 128 * APK + 2 * 32 * BPK) * 4)

__global__ void __launch_bounds__(256)
gemm_bf16x3_jobs(Jobs11 jobs, int njobs,
                 const uint32_t* __restrict__ whi, const uint32_t* __restrict__ wlo)
{
    extern __shared__ uint32_t sm[];

    int bid = blockIdx.x;
    int j = 0;
    while (j + 1 < njobs && bid >= jobs.j[j + 1].blk0) j++;
    const GemmJob& J = jobs.j[j];

    int tid  = threadIdx.x;
    int lane = tid & 31, warp = tid >> 5;
    int wm = warp & 1, wn = warp >> 1;     // 2 x 4 warp grid, warp tile 64x32
    int g = lane >> 2, t = lane & 3;
    int row0 = (bid - J.blk0) * 128;
    bool doGelu = (J.epi & 4) != 0;
    const uint32_t* WH = whi + (size_t)J.mat * 64 * 128;
    const uint32_t* WL = wlo + (size_t)J.mat * 64 * 128;

    float acc[4][4][4];
    #pragma unroll
    for (int a = 0; a < 4; a++)
        #pragma unroll
        for (int b = 0; b < 4; b++)
            #pragma unroll
            for (int c = 0; c < 4; c++) acc[a][b][c] = 0.f;

    #pragma unroll
    for (int ch = 0; ch < 2; ch++) {
        int k0 = ch * 64;
        // ---- A tile: 128 rows x 64 k, split+pack to bf16 hi/lo pairs ----
        {
            int r  = tid >> 4;            // 0..15
            int c4 = (tid & 15) * 4;      // 0..60 (k offset)
            #pragma unroll
            for (int p = 0; p < 8; p++) {
                int rr = r + p * 16;
                int gr = row0 + rr;
                float4 v = make_float4(0.f, 0.f, 0.f, 0.f);
                if (gr < J.M) v = *(const float4*)(J.A + (size_t)gr * 128 + k0 + c4);
                if (doGelu) {
                    v.x = gelu_tanh(v.x); v.y = gelu_tanh(v.y);
                    v.z = gelu_tanh(v.z); v.w = gelu_tanh(v.w);
                }
                uint32_t h0, l0, h1, l1;
                bf16x3_pack(v.x, v.y, h0, l0);
                bf16x3_pack(v.z, v.w, h1, l1);
                int base = rr * APK + (c4 >> 1);
                *(uint2*)&sm[A_HI + base] = make_uint2(h0, h1);
                *(uint2*)&sm[A_LO + base] = make_uint2(l0, l1);
            }
        }
        // ---- B tile: copy pre-split weights [32 kpairs][128 cols] ----
        {
            int kp0 = tid >> 5;           // 0..7
            int c4  = (tid & 31) * 4;     // 0..124
            const uint32_t* WHc = WH + ch * 32 * 128;
            const uint32_t* WLc = WL + ch * 32 * 128;
            #pragma unroll
            for (int p = 0; p < 4; p++) {
                int kp = kp0 + p * 8;
                uint4 hv = *(const uint4*)&WHc[kp * 128 + c4];
                uint4 lv = *(const uint4*)&WLc[kp * 128 + c4];
                *(uint4*)&sm[B_HI + kp * BPK + c4] = hv;
                *(uint4*)&sm[B_LO + kp * BPK + c4] = lv;
            }
        }
        __syncthreads();

        #pragma unroll
        for (int ks = 0; ks < 4; ks++) {      // 4 x k16 steps per 64-k chunk
            int kp = ks * 8;
            uint32_t ahi[4][4], alo[4][4];
            #pragma unroll
            for (int mf = 0; mf < 4; mf++) {
                int rm = wm * 64 + mf * 16;
                int i0 = (rm + g)     * APK + kp + t;
                int i1 = (rm + g + 8) * APK + kp + t;
                ahi[mf][0] = sm[A_HI + i0];
                ahi[mf][1] = sm[A_HI + i1];
                ahi[mf][2] = sm[A_HI + i0 + 4];
                ahi[mf][3] = sm[A_HI + i1 + 4];
                alo[mf][0] = sm[A_LO + i0];
                alo[mf][1] = sm[A_LO + i1];
                alo[mf][2] = sm[A_LO + i0 + 4];
                alo[mf][3] = sm[A_LO + i1 + 4];
            }
            #pragma unroll
            for (int nf = 0; nf < 4; nf++) {
                int cn = wn * 32 + nf * 8 + g;
                uint32_t bh0 = sm[B_HI + (kp + t)     * BPK + cn];
                uint32_t bh1 = sm[B_HI + (kp + t + 4) * BPK + cn];
                uint32_t bl0 = sm[B_LO + (kp + t)     * BPK + cn];
                uint32_t bl1 = sm[B_LO + (kp + t + 4) * BPK + cn];
                #pragma unroll
                for (int mf = 0; mf < 4; mf++) {
                    mma_bf16(acc[mf][nf], ahi[mf], bh0, bh1);
                    mma_bf16(acc[mf][nf], ahi[mf], bl0, bl1);
                    mma_bf16(acc[mf][nf], alo[mf], bh0, bh1);
                }
            }
        }
        __syncthreads();
    }

    // epilogue
    float beta = 1.f, omb = 0.f;
    if (J.epi & 2) {
        float sv = *J.skipv;
        beta = 1.f / (1.f + __expf(-sv));
        omb  = 1.f - beta;
    }
    bool relu = (J.epi & 1) || (J.epi & 2);

    #pragma unroll
    for (int nf = 0; nf < 4; nf++) {
        int col = wn * 32 + nf * 8 + t * 2;
        float bc0 = J.bias[col], bc1 = J.bias[col + 1];
        #pragma unroll
        for (int mf = 0; mf < 4; mf++) {
            int r0 = row0 + wm * 64 + mf * 16 + g;
            int r1 = r0 + 8;
            float o00 = acc[mf][nf][0] + bc0, o01 = acc[mf][nf][1] + bc1;
            float o10 = acc[mf][nf][2] + bc0, o11 = acc[mf][nf][3] + bc1;
            if (J.epi & 2) {
                if (r0 < J.M) {
                    float2 s = *(const float2*)(J.skipx + (size_t)r0 * 128 + col);
                    o00 = beta * o00 + omb * s.x;
                    o01 = beta * o01 + omb * s.y;
                }
                if (r1 < J.M) {
                    float2 s = *(const float2*)(J.skipx + (size_t)r1 * 128 + col);
                    o10 = beta * o10 + omb * s.x;
                    o11 = beta * o11 + omb * s.y;
                }
            }
            if (relu) {
                o00 = fmaxf(o00, 0.f); o01 = fmaxf(o01, 0.f);
                o10 = fmaxf(o10, 0.f); o11 = fmaxf(o11, 0.f);
            }
            if (r0 < J.M) *(float2*)(J.Out + (size_t)r0 * 128 + col) = make_float2(o00, o01);
            if (r1 < J.M) *(float2*)(J.Out + (size_t)r1 * 128 + col) = make_float2(o10, o11);
        }
    }
}

// ---------------- fused Q/K/V projection: A packed once, 3-5 weight matrices ----------------
// All outputs use plain bias epilogue (epi=0 class only). A resident full-K in smem.
struct QkvGroup {
    const float* A;
    const float* bias[5];
    float* out[5];
    int mat[5];
    int M, blk0, nrep, _pad;
};
struct QkvJobs { QkvGroup g[3]; };

#define APK2 68    // uint32 stride per A row: 64 kpairs + 4 pad
#define A2_HI 0
#define A2_LO (128 * APK2)
#define B2_HI (2 * 128 * APK2)
#define B2_LO (2 * 128 * APK2 + 32 * BPK)
#define QKV_SMEM ((2 * 128 * APK2 + 2 * 32 * BPK) * 4)

__global__ void __launch_bounds__(256)
gemm_qkv(QkvJobs jobs, const uint32_t* __restrict__ whi, const uint32_t* __restrict__ wlo)
{
    extern __shared__ uint32_t sm[];

    int bid = blockIdx.x;
    int gI = 0;
    while (gI + 1 < 3 && bid >= jobs.g[gI + 1].blk0) gI++;
    const QkvGroup& G = jobs.g[gI];

    int tid  = threadIdx.x;
    int lane = tid & 31, warp = tid >> 5;
    int wm = warp & 1, wn = warp >> 1;
    int g = lane >> 2, t = lane & 3;
    int row0 = (bid - G.blk0) * 128;

    // ---- A tile: 128 rows x 128 k, pack ONCE ----
    {
        int r  = tid >> 5;             // 0..7
        int c4 = (tid & 31) * 4;       // 0..124
        #pragma unroll
        for (int p = 0; p < 16; p++) {
            int rr = r + p * 8;
            int gr = row0 + rr;
            float4 v = make_float4(0.f, 0.f, 0.f, 0.f);
            if (gr < G.M) v = *(const float4*)(G.A + (size_t)gr * 128 + c4);
            uint32_t h0, l0, h1, l1;
            bf16x3_pack(v.x, v.y, h0, l0);
            bf16x3_pack(v.z, v.w, h1, l1);
            int base = rr * APK2 + (c4 >> 1);
            *(uint2*)&sm[A2_HI + base] = make_uint2(h0, h1);
            *(uint2*)&sm[A2_LO + base] = make_uint2(l0, l1);
        }
    }

    for (int rep = 0; rep < G.nrep; rep++) {
        const uint32_t* WH = whi + (size_t)G.mat[rep] * 64 * 128;
        const uint32_t* WL = wlo + (size_t)G.mat[rep] * 64 * 128;

        float acc[4][4][4];
        #pragma unroll
        for (int a = 0; a < 4; a++)
            #pragma unroll
            for (int b = 0; b < 4; b++)
                #pragma unroll
                for (int c = 0; c < 4; c++) acc[a][b][c] = 0.f;

        #pragma unroll 1
        for (int ch = 0; ch < 2; ch++) {
            __syncthreads();   // previous readers of B done (also orders A pack on first pass)
            {
                int kp0 = tid >> 5;
                int c4  = (tid & 31) * 4;
                const uint32_t* WHc = WH + ch * 32 * 128;
                const uint32_t* WLc = WL + ch * 32 * 128;
                #pragma unroll
                for (int p = 0; p < 4; p++) {
                    int kp = kp0 + p * 8;
                    uint4 hv = *(const uint4*)&WHc[kp * 128 + c4];
                    uint4 lv = *(const uint4*)&WLc[kp * 128 + c4];
                    *(uint4*)&sm[B2_HI + kp * BPK + c4] = hv;
                    *(uint4*)&sm[B2_LO + kp * BPK + c4] = lv;
                }
            }
            __syncthreads();

            #pragma unroll
            for (int ks = 0; ks < 4; ks++) {
                int kp  = ks * 8;            // B chunk-local k-pair base
                int kpg = ch * 32 + kp;      // A global k-pair base
                uint32_t ahi[4][4], alo[4][4];
                #pragma unroll
                for (int mf = 0; mf < 4; mf++) {
                    int rm = wm * 64 + mf * 16;
                    int i0 = (rm + g)     * APK2 + kpg + t;
                    int i1 = (rm + g + 8) * APK2 + kpg + t;
                    ahi[mf][0] = sm[A2_HI + i0];
                    ahi[mf][1] = sm[A2_HI + i1];
                    ahi[mf][2] = sm[A2_HI + i0 + 4];
                    ahi[mf][3] = sm[A2_HI + i1 + 4];
                    alo[mf][0] = sm[A2_LO + i0];
                    alo[mf][1] = sm[A2_LO + i1];
                    alo[mf][2] = sm[A2_LO + i0 + 4];
                    alo[mf][3] = sm[A2_LO + i1 + 4];
                }
                #pragma unroll
                for (int nf = 0; nf < 4; nf++) {
                    int cn = wn * 32 + nf * 8 + g;
                    uint32_t bh0 = sm[B2_HI + (kp + t)     * BPK + cn];
                    uint32_t bh1 = sm[B2_HI + (kp + t + 4) * BPK + cn];
                    uint32_t bl0 = sm[B2_LO + (kp + t)     * BPK + cn];
                    uint32_t bl1 = sm[B2_LO + (kp + t + 4) * BPK + cn];
                    #pragma unroll
                    for (int mf = 0; mf < 4; mf++) {
                        mma_bf16(acc[mf][nf], ahi[mf], bh0, bh1);
                        mma_bf16(acc[mf][nf], ahi[mf], bl0, bl1);
                        mma_bf16(acc[mf][nf], alo[mf], bh0, bh1);
                    }
                }
            }
        }

        // ---- plain bias epilogue ----
        const float* bias = G.bias[rep];
        float* Out = G.out[rep];
        #pragma unroll
        for (int nf = 0; nf < 4; nf++) {
            int col = wn * 32 + nf * 8 + t * 2;
            float bc0 = bias[col], bc1 = bias[col + 1];
            #pragma unroll
            for (int mf = 0; mf < 4; mf++) {
                int r0 = row0 + wm * 64 + mf * 16 + g;
                int r1 = r0 + 8;
                if (r0 < G.M)
                    *(float2*)(Out + (size_t)r0 * 128 + col) =
                        make_float2(acc[mf][nf][0] + bc0, acc[mf][nf][1] + bc1);
                if (r1 < G.M)
                    *(float2*)(Out + (size_t)r1 * 128 + col) =
                        make_float2(acc[mf][nf][2] + bc0, acc[mf][nf][3] + bc1);
            }
        }
    }
}

// ---------------- scalar GEMM for the final [128 x 64] projection ----------------
__global__ void __launch_bounds__(256)
gemm_out64(const float* __restrict__ A, const float* __restrict__ W,
           const float* __restrict__ bias, float* __restrict__ Out, int M)
{
    constexpr int BN = 64, CT = BN / 4, BM = (256 / CT) * 8, BK = 32, AP = BM + 4;
    __shared__ float As[BK][AP];
    __shared__ float Bs[BK][BN];

    int tid = threadIdx.x;
    int row0 = blockIdx.x * BM;
    int trow = (tid / CT) * 8;
    int tcol = (tid % CT) * 4;

    float acc[8][4];
    #pragma unroll
    for (int r = 0; r < 8; r++)
        #pragma unroll
        for (int c = 0; c < 4; c++) acc[r][c] = 0.f;

    for (int k0 = 0; k0 < 128; k0 += BK) {
        #pragma unroll
        for (int i = 0; i < (BM * 8) / 256; ++i) {
            int id = tid + i * 256;
            int r = id >> 3, kq = id & 7;
            float4 v = make_float4(0.f, 0.f, 0.f, 0.f);
            int gr = row0 + r;
            if (gr < M) v = *(const float4*)(A + (size_t)gr * 128 + k0 + kq * 4);
            As[kq * 4 + 0][r] = v.x; As[kq * 4 + 1][r] = v.y;
            As[kq * 4 + 2][r] = v.z; As[kq * 4 + 3][r] = v.w;
        }
        #pragma unroll
        for (int i = 0; i < (8 * BN) / 256; ++i) {
            int id = tid + i * 256;
            int kr = id / CT, c4 = (id % CT) * 4;
            *(float4*)&Bs[kr][c4] = *(const float4*)(W + (size_t)(k0 + kr) * BN + c4);
        }
        __syncthreads();
        #pragma unroll
        for (int k = 0; k < BK; ++k) {
            float4 b = *(float4*)&Bs[k][tcol];
            #pragma unroll
            for (int r = 0; r < 8; r++) {
                float a = As[k][trow + r];
                acc[r][0] += a * b.x; acc[r][1] += a * b.y;
                acc[r][2] += a * b.z; acc[r][3] += a * b.w;
            }
        }
        __syncthreads();
    }
    float b0 = bias[tcol], b1 = bias[tcol + 1], b2 = bias[tcol + 2], b3 = bias[tcol + 3];
    #pragma unroll
    for (int r = 0; r < 8; r++) {
        int gr = row0 + trow + r;
        if (gr >= M) break;
        float4 o = make_float4(acc[r][0] + b0, acc[r][1] + b1, acc[r][2] + b2, acc[r][3] + b3);
        *(float4*)(Out + (size_t)gr * BN + tcol) = o;
    }
}

// ---------------- host orchestration ----------------
static inline int nb128(int m) { return (m + 127) / 128; }

extern "C" void kernel_launch(void* const* d_in, const int* in_sizes, int n_in,
                              void* d_out, int out_size)
{
    const float* x_in[3] = {(const float*)d_in[0], (const float*)d_in[1], (const float*)d_in[2]};
    const int* esrc[4] = {(const int*)d_in[3], (const int*)d_in[5], (const int*)d_in[7], (const int*)d_in[9]};
    const int* edst[4] = {(const int*)d_in[4], (const int*)d_in[6], (const int*)d_in[8], (const int*)d_in[10]};
    const float* lin_w = (const float*)d_in[11];
    const float* lin_b = (const float*)d_in[12];
    const float* kw    = (const float*)d_in[13];
    const float* qw    = (const float*)d_in[14];
    const float* vw    = (const float*)d_in[15];
    const float* aw    = (const float*)d_in[16];
    const float* kb    = (const float*)d_in[17];
    const float* qb    = (const float*)d_in[18];
    const float* vb    = (const float*)d_in[19];
    const float* ab    = (const float*)d_in[20];
    const float* a_rel = (const float*)d_in[21];
    const float* m_rel = (const float*)d_in[22];
    const float* p_rel = (const float*)d_in[23];
    const float* skip  = (const float*)d_in[24];
    const float* out_w = (const float*)d_in[25];
    const float* out_b = (const float*)d_in[26];
    float* out = (float*)d_out;

    float *xs, *q, *agg, *ket, *vet, *kwc, *vwc, *kbc, *vbc;
    int *cnt, *off, *woff, *part, *ssrc;
    uint32_t *whi, *wlo;
    cudaGetSymbolAddress((void**)&xs,   g_xs);
    cudaGetSymbolAddress((void**)&q,    g_q);
    cudaGetSymbolAddress((void**)&agg,  g_agg);
    cudaGetSymbolAddress((void**)&ket,  g_ket);
    cudaGetSymbolAddress((void**)&vet,  g_vet);
    cudaGetSymbolAddress((void**)&cnt,  g_cnt);
    cudaGetSymbolAddress((void**)&off,  g_off);
    cudaGetSymbolAddress((void**)&woff, g_woff);
    cudaGetSymbolAddress((void**)&part, g_part);
    cudaGetSymbolAddress((void**)&ssrc, g_ssrc);
    cudaGetSymbolAddress((void**)&kwc,  g_kwc);
    cudaGetSymbolAddress((void**)&vwc,  g_vwc);
    cudaGetSymbolAddress((void**)&kbc,  g_kbc);
    cudaGetSymbolAddress((void**)&vbc,  g_vbc);
    cudaGetSymbolAddress((void**)&whi,  g_whi);
    cudaGetSymbolAddress((void**)&wlo,  g_wlo);

    cudaFuncSetAttribute(gemm_bf16x3_jobs, cudaFuncAttributeMaxDynamicSharedMemorySize, GEMM_SMEM);
    cudaFuncSetAttribute(gemm_qkv, cudaFuncAttributeMaxDynamicSharedMemorySize, QKV_SMEM);

    // ---- CSR build (edges are layer-invariant: build once) ----
    cudaMemsetAsync(cnt, 0, DROWS * sizeof(int));
    hist4_kernel<<<(ETOT + 255) / 256, 256>>>(edst[0], edst[1], edst[2], edst[3], cnt);
    scan_block<<<(DROWS + 1023) / 1024, 1024>>>(cnt, off, part);
    scan_part<<<1, 32>>>(part, (DROWS + 1023) / 1024);
    scan_add<<<(DROWS + 256) / 256, 256>>>(off, part, woff);
    scatter4_kernel<<<(ETOT + 255) / 256, 256>>>(esrc[0], edst[0], esrc[1], edst[1],
                                                 esrc[2], edst[2], esrc[3], edst[3],
                                                 woff, ssrc);

    // ---- fold a_rel/m_rel into K/V weights, then pre-split all weights to bf16 hi/lo ----
    wcomb_kernel<<<8, 256>>>(kw, kb, vw, vb, a_rel, m_rel);
    {
        WSrc ws;
        for (int i = 0; i < 3; i++) ws.w[i] = lin_w + (size_t)i * C * C;                       // 0..2
        for (int li = 0; li < 6; li++) ws.w[3 + li] = qw + (size_t)li * C * C;                 // 3..8
        for (int le = 0; le < 8; le++) ws.w[9 + le] = kwc + (size_t)le * C * C;                // 9..16
        for (int le = 0; le < 8; le++) ws.w[17 + le] = vwc + (size_t)le * C * C;               // 17..24
        for (int li = 0; li < 6; li++) ws.w[25 + li] = aw + (size_t)li * C * C;                // 25..30
        wsplit_kernel<<<NMAT, 256>>>(ws);
    }

    // ---- input linear + relu (3 jobs, one launch, proven kernel) ----
    {
        Jobs11 js{}; int nj = 0, blk = 0;
        for (int i = 0; i < 3; i++) {
            GemmJob& J = js.j[nj++];
            J.A = x_in[i]; J.mat = i; J.bias = lin_b + i * C;
            J.Out = xs + (size_t)XOFF[i] * C; J.M = NNh[i]; J.blk0 = blk; J.epi = 1;
            J.skipx = nullptr; J.skipv = nullptr;
            blk += nb128(NNh[i]);
        }
        gemm_bf16x3_jobs<<<blk, 256, GEMM_SMEM>>>(js, nj, whi, wlo);
    }

    static const int KOFFh[4] = {KOFF0, KOFF1, KOFF2, KOFF3};
    for (int l = 0; l < NLAYER; l++) {
        // ---- fused Q/K/V projections: one block-group per node type, A packed once ----
        {
            QkvJobs js{}; int blk = 0;
            // group 0: poi -> Q_poi, K_et0, V_et0
            {
                QkvGroup& G = js.g[0];
                G.A = xs; G.M = NNh[0]; G.blk0 = blk; G.nrep = 3;
                G.mat[0] = 3 + l * 3 + 0;  G.bias[0] = qb + (l * 3 + 0) * C;  G.out[0] = q;
                G.mat[1] = 9 + l * 4 + 0;  G.bias[1] = kbc + (l * 4 + 0) * C; G.out[1] = ket + (size_t)KOFFh[0] * C;
                G.mat[2] = 17 + l * 4 + 0; G.bias[2] = vbc + (l * 4 + 0) * C; G.out[2] = vet + (size_t)KOFFh[0] * C;
                blk += nb128(NNh[0]);
            }
            // group 1: road -> Q_road, K_et1, V_et1, K_et2, V_et2
            {
                QkvGroup& G = js.g[1];
                G.A = xs + (size_t)XOFF[1] * C; G.M = NNh[1]; G.blk0 = blk; G.nrep = 5;
                G.mat[0] = 3 + l * 3 + 1;  G.bias[0] = qb + (l * 3 + 1) * C;  G.out[0] = q + (size_t)XOFF[1] * C;
                G.mat[1] = 9 + l * 4 + 1;  G.bias[1] = kbc + (l * 4 + 1) * C; G.out[1] = ket + (size_t)KOFFh[1] * C;
                G.mat[2] = 17 + l * 4 + 1; G.bias[2] = vbc + (l * 4 + 1) * C; G.out[2] = vet + (size_t)KOFFh[1] * C;
                G.mat[3] = 9 + l * 4 + 2;  G.bias[3] = kbc + (l * 4 + 2) * C; G.out[3] = ket + (size_t)KOFFh[2] * C;
                G.mat[4] = 17 + l * 4 + 2; G.bias[4] = vbc + (l * 4 + 2) * C; G.out[4] = vet + (size_t)KOFFh[2] * C;
                blk += nb128(NNh[1]);
            }
            // group 2: region -> Q_region, K_et3, V_et3
            {
                QkvGroup& G = js.g[2];
                G.A = xs + (size_t)XOFF[2] * C; G.M = NNh[2]; G.blk0 = blk; G.nrep = 3;
                G.mat[0] = 3 + l * 3 + 2;  G.bias[0] = qb + (l * 3 + 2) * C;  G.out[0] = q + (size_t)XOFF[2] * C;
                G.mat[1] = 9 + l * 4 + 3;  G.bias[1] = kbc + (l * 4 + 3) * C; G.out[1] = ket + (size_t)KOFFh[3] * C;
                G.mat[2] = 17 + l * 4 + 3; G.bias[2] = vbc + (l * 4 + 3) * C; G.out[2] = vet + (size_t)KOFFh[3] * C;
                blk += nb128(NNh[2]);
            }
            gemm_qkv<<<blk, 256, QKV_SMEM>>>(js, whi, wlo);
        }

        // ---- fused attention (online softmax, no atomics) ----
        attn_fused<<<(NTOT * 32 + 255) / 256, 256>>>(q, ket, vet, off, agg, p_rel, l);

        // ---- attn-out projection, gelu fused on A, skip-gate + relu epilogue ----
        {
            Jobs11 js{}; int nj = 0, blk = 0;
            for (int i = 0; i < 3; i++) {
                GemmJob& J = js.j[nj++];
                J.A = agg + (size_t)XOFF[i] * C;
                J.mat = 25 + l * 3 + i;
                J.bias = ab + (l * 3 + i) * C;
                J.Out = xs + (size_t)XOFF[i] * C;
                J.skipx = xs + (size_t)XOFF[i] * C;
                J.skipv = skip + l * 3 + i;
                J.M = NNh[i]; J.blk0 = blk; J.epi = 2 | 4;
                blk += nb128(NNh[i]);
            }
            gemm_bf16x3_jobs<<<blk, 256, GEMM_SMEM>>>(js, nj, whi, wlo);
        }
    }

    // ---- final output projection [N,128] @ [128,64] ----
    for (int i = 0; i < 3; i++) {
        dim3 grid((NNh[i] + 127) / 128);
        gemm_out64<<<grid, 256>>>(xs + (size_t)XOFF[i] * C, out_w, out_b,
                                  out + (size_t)XOFF[i] * OUTC, NNh[i]);
    }
}